// round 17
// baseline (speedup 1.0000x reference)
#include <cuda_runtime.h>
#include <cuda_fp16.h>
#include <math.h>
#include <stdint.h>

#define SDIM 2048
#define EDIM 2048
#define NH   16
#define NKV  4
#define DH   128
#define NHG  12
#define RDIM 32
#define NSYM 4
#define NOUT 3840
#define CQ   0
#define CK   2048
#define CV   2560
#define CRQ  3072
#define CRK  3456
#define KQ   192

// fattn smem offsets
#define QOFF  0u        // 3 x 8KB q subtiles (64x64)
#define KBOFF 24576u    // 2 x 16KB kb bufs (128x64)
#define VOFF  57344u    // 2 x 16KB vth bufs (128x64)
#define POFF  90112u    // 2 x 8KB P subtiles (64x64)
#define RSOFF 106496u   // 64 floats
#define FSMEM 106752u

static __device__ float g_pr[SDIM*NOUT];
static __device__ __half g_xh [SDIM*EDIM];
static __device__ __half g_wh [(size_t)NOUT*EDIM];
static __device__ __half g_woh[(size_t)EDIM*EDIM];
static __device__ __half g_aoh[(size_t)SDIM*EDIM];
static __device__ __half g_qa [(size_t)NH*SDIM*KQ];
static __device__ __half g_kb [(size_t)NH*SDIM*KQ];
static __device__ __half g_vth[(size_t)NKV*DH*SDIM];

// ---------------- PTX helpers ----------------
__device__ __forceinline__ uint32_t smem_u32(const void* p) {
    uint32_t a;
    asm("{ .reg .u64 t; cvta.to.shared.u64 t, %1; cvt.u32.u64 %0, t; }" : "=r"(a) : "l"(p));
    return a;
}
__device__ __forceinline__ void cpa16(uint32_t d, const void* g) {
    asm volatile("cp.async.cg.shared.global [%0], [%1], 16;" :: "r"(d), "l"(g));
}
__device__ __forceinline__ void cp_commit() { asm volatile("cp.async.commit_group;" ::: "memory"); }
template<int N> __device__ __forceinline__ void cp_wait() {
    asm volatile("cp.async.wait_group %0;" :: "n"(N) : "memory");
}
__device__ __forceinline__ void ldm_x4(uint32_t& r0, uint32_t& r1, uint32_t& r2, uint32_t& r3,
                                       uint32_t addr) {
    asm volatile("ldmatrix.sync.aligned.m8n8.x4.shared.b16 {%0,%1,%2,%3}, [%4];"
                 : "=r"(r0), "=r"(r1), "=r"(r2), "=r"(r3) : "r"(addr));
}
__device__ __forceinline__ void mma_f16(float* d, const uint32_t* a, const uint32_t* b) {
    asm volatile("mma.sync.aligned.m16n8k16.row.col.f32.f16.f16.f32 "
                 "{%0,%1,%2,%3}, {%4,%5,%6,%7}, {%8,%9}, {%0,%1,%2,%3};"
                 : "+f"(d[0]), "+f"(d[1]), "+f"(d[2]), "+f"(d[3])
                 : "r"(a[0]), "r"(a[1]), "r"(a[2]), "r"(a[3]), "r"(b[0]), "r"(b[1]));
}
__device__ __forceinline__ void sbody1(const float* s, __half* dh, int i) {
    float2 v = ((const float2*)s)[i];
    __half h0 = __float2half_rn(v.x), h1 = __float2half_rn(v.y);
    ((uint32_t*)dh)[i] = (uint32_t)__half_as_ushort(h0)
                       | ((uint32_t)__half_as_ushort(h1) << 16);
}

// ---------------- merged split ----------------
__global__ __launch_bounds__(256) void split_all(
    const float* __restrict__ x,  const float* __restrict__ wq,
    const float* __restrict__ wk, const float* __restrict__ wv,
    const float* __restrict__ wrq, const float* __restrict__ wrk,
    const float* __restrict__ wo)
{
    int i = blockIdx.x * 256 + threadIdx.x;
    const int E0 = 2097152, E1 = 4194304, E2 = 4718592, E3 = 5242880,
              E4 = 5636096, E5 = 6029312, E6 = 8126464;
    if      (i < E0) sbody1(x,   g_xh, i);
    else if (i < E1) sbody1(wq,  g_wh + (size_t)CQ  * EDIM, i - E0);
    else if (i < E2) sbody1(wk,  g_wh + (size_t)CK  * EDIM, i - E1);
    else if (i < E3) sbody1(wv,  g_wh + (size_t)CV  * EDIM, i - E2);
    else if (i < E4) sbody1(wrq, g_wh + (size_t)CRQ * EDIM, i - E3);
    else if (i < E5) sbody1(wrk, g_wh + (size_t)CRK * EDIM, i - E4);
    else if (i < E6) sbody1(wo,  g_woh, i - E5);
}

// ---------------- shared machinery ----------------
#define GEMM_PREAMBLE                                                           \
    extern __shared__ __align__(1024) char dsm[];                               \
    const uint32_t sb = smem_u32(dsm);                                          \
    const int tid = threadIdx.x;                                                \
    const int l = tid & 31, wid = tid >> 5;                                     \
    const int cch = tid & 7;                                                    \
    const int akh = (l >> 4);                                                   \
    const int bkh = (l >> 3) & 1;                                               \
    const int lsw = l & 7;

#define LOAD128(base, P, ld, step) do {                                         \
    const __half* G = (P) + (size_t)(step) * 64;                                \
    _Pragma("unroll")                                                           \
    for (int it = 0; it < 4; it++) {                                            \
        int row = (tid >> 3) + 32 * it;                                         \
        uint32_t sw = row * 128u + 16u * (cch ^ (row & 7));                     \
        cpa16((base) + sw, G + (size_t)row * (ld) + cch * 8);                   \
    } } while (0)

#define LOAD64(base, P, ld, step) do {                                          \
    const __half* G = (P) + (size_t)(step) * 64;                                \
    _Pragma("unroll")                                                           \
    for (int it = 0; it < 2; it++) {                                            \
        int row = (tid >> 3) + 32 * it;                                         \
        uint32_t sw = row * 128u + 16u * (cch ^ (row & 7));                     \
        cpa16((base) + sw, G + (size_t)row * (ld) + cch * 8);                   \
    } } while (0)

// 64-row x 128-col tile step: warp 32x32, ratio 2.0
#define INNER8(ACC, Ab, Bb)                                                     \
    _Pragma("unroll")                                                           \
    for (int kk = 0; kk < 4; kk++) {                                            \
        uint32_t bf[4][2], af[2][4];                                            \
        _Pragma("unroll")                                                       \
        for (int np = 0; np < 2; np++) {                                        \
            uint32_t r0, r1, r2, r3;                                            \
            ldm_x4(r0, r1, r2, r3,                                              \
                   (Bb) + (uint32_t)(br + np * 16) * 128u + 16u * (((kk << 1) + bkh) ^ lsw)); \
            bf[2*np][0] = r0; bf[2*np][1] = r1; bf[2*np+1][0] = r2; bf[2*np+1][1] = r3; \
        }                                                                       \
        _Pragma("unroll")                                                       \
        for (int tm = 0; tm < 2; tm++)                                          \
            ldm_x4(af[tm][0], af[tm][1], af[tm][2], af[tm][3],                  \
                   (Ab) + (uint32_t)(ar + tm * 16) * 128u + 16u * (((kk << 1) + akh) ^ lsw)); \
        _Pragma("unroll")                                                       \
        for (int tm = 0; tm < 2; tm++)                                          \
            _Pragma("unroll")                                                   \
            for (int tn = 0; tn < 4; tn++) mma_f16(ACC[tm][tn], af[tm], bf[tn]); \
    }

// ---------------- single-product fp16 GEMM (proj / Wo) ----------------
__global__ __launch_bounds__(256, 3) void gemm1(
    const __half* __restrict__ Ah, const __half* __restrict__ Bh,
    float* __restrict__ C, int ldc, int K)
{
    GEMM_PREAMBLE
    const int wm = wid & 1, wn = wid >> 1;
    const int m0 = blockIdx.y << 6, n0 = blockIdx.x << 7;
    const int steps = K >> 6;
    const __half* Ah_ = Ah + (size_t)m0 * K;
    const __half* Bh_ = Bh + (size_t)n0 * K;

    float acc[2][4][4];
#pragma unroll
    for (int i = 0; i < 2; i++)
#pragma unroll
        for (int j = 0; j < 4; j++)
#pragma unroll
            for (int r = 0; r < 4; r++) acc[i][j][r] = 0.f;

    const int ar = wm * 32 + (l & 7) + (l & 8);
    const int br = wn * 32 + (l & 7) + 8 * (l >> 4);

    LOAD64(sb, Ah_, K, 0);
    LOAD128(sb + 8192u, Bh_, K, 0);
    cp_commit();

    for (int s = 0; s < steps; s++) {
        cp_wait<0>();
        __syncthreads();
        if (s + 1 < steps) {
            uint32_t b2 = sb + ((s + 1) & 1) * 24576u;
            LOAD64(b2, Ah_, K, s + 1);
            LOAD128(b2 + 8192u, Bh_, K, s + 1);
            cp_commit();
        }
        const uint32_t Ast = sb + (s & 1) * 24576u;
        const uint32_t Bst = Ast + 8192u;
        INNER8(acc, Ast, Bst)
    }
    const int er = m0 + wm * 32 + (l >> 2);
    const int ec = n0 + wn * 32 + 2 * (l & 3);
#pragma unroll
    for (int tm = 0; tm < 2; tm++)
#pragma unroll
        for (int tn = 0; tn < 4; tn++) {
            float* p0 = C + (size_t)(er + tm * 16) * ldc + ec + tn * 8;
            float* p1 = C + (size_t)(er + tm * 16 + 8) * ldc + ec + tn * 8;
            *(float2*)p0 = make_float2(acc[tm][tn][0], acc[tm][tn][1]);
            *(float2*)p1 = make_float2(acc[tm][tn][2], acc[tm][tn][3]);
        }
}

// ---------------- fused attention: S = q kb^T, P = exp/16, O += P V^T ------
__global__ __launch_bounds__(256, 2) void fattn()
{
    GEMM_PREAMBLE
    float* rs_sm = (float*)(dsm + RSOFF);
    const int wm = wid & 1, wn = wid >> 1;
    const int h = blockIdx.y;
    const int nst = (h < NHG) ? 3 : 2;
    const __half* Kb_ = g_kb + (size_t)h * SDIM * KQ;
    const __half* Vh_ = g_vth + (size_t)(h >> 2) * DH * SDIM;

    const int ar = wm * 32 + (l & 7) + (l & 8);
    const int br = wn * 32 + (l & 7) + 8 * (l >> 4);

    for (int half = 0; half < 2; half++) {
        const int mt = half ? 31 - (int)blockIdx.x : (int)blockIdx.x;
        const int m0 = mt << 6;
        const int jlast = m0 >> 7;

        if (tid < 64) rs_sm[tid] = 0.f;

        float accO[2][4][4];
#pragma unroll
        for (int i = 0; i < 2; i++)
#pragma unroll
            for (int j = 0; j < 4; j++)
#pragma unroll
                for (int r = 0; r < 4; r++) accO[i][j][r] = 0.f;
        float psum[2][2] = {{0.f, 0.f}, {0.f, 0.f}};

        const __half* Qp = g_qa + ((size_t)h * SDIM + m0) * KQ;
        for (int st = 0; st < nst; st++) LOAD64(sb + QOFF + st * 8192u, Qp, KQ, st);
        LOAD128(sb + KBOFF, Kb_, KQ, 0);
        cp_commit();

        for (int j = 0; j <= jlast; j++) {
            const __half* Kjp = Kb_ + (size_t)(j * 128) * KQ;
            float accS[2][4][4];
#pragma unroll
            for (int i = 0; i < 2; i++)
#pragma unroll
                for (int jj = 0; jj < 4; jj++)
#pragma unroll
                    for (int r = 0; r < 4; r++) accS[i][jj][r] = 0.f;

            // ---- S phase ----
            for (int st = 0; st < nst; st++) {
                cp_wait<0>();
                __syncthreads();
                if (st + 1 < nst)
                    LOAD128(sb + KBOFF + (uint32_t)(((st + 1) & 1) * 16384), Kjp, KQ, st + 1);
                else
                    LOAD128(sb + VOFF, Vh_, SDIM, j * 2);
                cp_commit();
                const uint32_t Ab = sb + QOFF + st * 8192u;
                const uint32_t Bb = sb + KBOFF + (st & 1) * 16384u;
                INNER8(accS, Ab, Bb)
            }

            // ---- exp + mask + P store + rowsum partials ----
#pragma unroll
            for (int tm = 0; tm < 2; tm++) {
                const int r0 = wm * 32 + tm * 16 + (l >> 2);
                const int r1 = r0 + 8;
#pragma unroll
                for (int tn = 0; tn < 4; tn++) {
                    const int c = wn * 32 + tn * 8 + 2 * (l & 3);
                    const int gc = j * 128 + c;
                    const bool unm = (j < jlast);
                    const int g0 = m0 + r0, g1 = m0 + r1;
                    float e00 = (unm || gc     <= g0) ? __expf(accS[tm][tn][0]) * 0.0625f : 0.f;
                    float e01 = (unm || gc + 1 <= g0) ? __expf(accS[tm][tn][1]) * 0.0625f : 0.f;
                    float e10 = (unm || gc     <= g1) ? __expf(accS[tm][tn][2]) * 0.0625f : 0.f;
                    float e11 = (unm || gc + 1 <= g1) ? __expf(accS[tm][tn][3]) * 0.0625f : 0.f;
                    psum[tm][0] += e00 + e01;
                    psum[tm][1] += e10 + e11;
                    const uint32_t subb = POFF + (uint32_t)(c >> 6) * 8192u;
                    const int cin = c & 63;
                    const uint32_t bcol = 16u * (uint32_t)(((cin >> 3) ^ (r0 & 7)) & 7) + ((cin & 7) << 1);
                    const uint32_t bcol1 = 16u * (uint32_t)(((cin >> 3) ^ (r1 & 7)) & 7) + ((cin & 7) << 1);
                    __half2 v0; v0.x = __float2half_rn(e00); v0.y = __float2half_rn(e01);
                    __half2 v1; v1.x = __float2half_rn(e10); v1.y = __float2half_rn(e11);
                    *(__half2*)(dsm + subb + (uint32_t)r0 * 128u + bcol)  = v0;
                    *(__half2*)(dsm + subb + (uint32_t)r1 * 128u + bcol1) = v1;
                }
            }

            // ---- O phase ----
            for (int ss = 0; ss < 2; ss++) {
                cp_wait<0>();
                __syncthreads();
                if (ss == 0)
                    LOAD128(sb + VOFF + 16384u, Vh_, SDIM, j * 2 + 1);
                else if (j < jlast)
                    LOAD128(sb + KBOFF, Kb_ + (size_t)((j + 1) * 128) * KQ, KQ, 0);
                cp_commit();
                const uint32_t Ab = sb + POFF + ss * 8192u;
                const uint32_t Bb = sb + VOFF + ss * 16384u;
                INNER8(accO, Ab, Bb)
            }
        }

        // ---- rowsum reduce ----
#pragma unroll
        for (int tm = 0; tm < 2; tm++)
#pragma unroll
            for (int rr = 0; rr < 2; rr++) {
                float v = psum[tm][rr];
                v += __shfl_xor_sync(0xffffffffu, v, 1);
                v += __shfl_xor_sync(0xffffffffu, v, 2);
                if ((l & 3) == 0)
                    atomicAdd(&rs_sm[wm * 32 + tm * 16 + rr * 8 + (l >> 2)], v);
            }
        __syncthreads();

        // ---- normalize + store ----
#pragma unroll
        for (int tm = 0; tm < 2; tm++) {
            const int lr0 = wm * 32 + tm * 16 + (l >> 2);
            const float ir0 = 1.f / rs_sm[lr0];
            const float ir1 = 1.f / rs_sm[lr0 + 8];
            const int gr0 = m0 + lr0;
#pragma unroll
            for (int tn = 0; tn < 4; tn++) {
                const int c = h * DH + wn * 32 + tn * 8 + 2 * (l & 3);
                __half h00 = __float2half_rn(accO[tm][tn][0] * ir0);
                __half h01 = __float2half_rn(accO[tm][tn][1] * ir0);
                __half h10 = __float2half_rn(accO[tm][tn][2] * ir1);
                __half h11 = __float2half_rn(accO[tm][tn][3] * ir1);
                ((uint32_t*)g_aoh)[(size_t)gr0 * (EDIM/2) + (c >> 1)] =
                    (uint32_t)__half_as_ushort(h00) | ((uint32_t)__half_as_ushort(h01) << 16);
                ((uint32_t*)g_aoh)[(size_t)(gr0 + 8) * (EDIM/2) + (c >> 1)] =
                    (uint32_t)__half_as_ushort(h10) | ((uint32_t)__half_as_ushort(h11) << 16);
            }
        }
        __syncthreads();
    }
}

// ---------------- merged RMSNorm+RoPE fill + V transpose --------------------
__global__ __launch_bounds__(128) void normfill2(
    const float* __restrict__ qw, const float* __restrict__ kw,
    const float* __restrict__ gscale)
{
    const int s = blockIdx.x, y = blockIdx.y, d = threadIdx.x;
    __shared__ float sm[64][129];

    if (y >= NH + NKV) {                 // V transpose blocks
        const int kvh = y - (NH + NKV);
        const int jb = s;
        if (jb >= SDIM / 64) return;
        for (int jj = 0; jj < 64; jj++)
            sm[jj][d] = g_pr[(size_t)(jb * 64 + jj) * NOUT + CV + kvh * DH + d];
        __syncthreads();
        const int w = d >> 5, ln = d & 31;
        for (int dd = w; dd < DH; dd += 4) {
            __half h0 = __float2half_rn(sm[2*ln][dd]);
            __half h1 = __float2half_rn(sm[2*ln+1][dd]);
            uint32_t* oh = (uint32_t*)(g_vth + (size_t)(kvh * DH + dd) * SDIM + jb * 64);
            oh[ln] = (uint32_t)__half_as_ushort(h0) | ((uint32_t)__half_as_ushort(h1) << 16);
        }
        return;
    }

    const bool isQ = (y < NH);
    const int hq = y, kvh = y - NH;
    const float* w = isQ ? qw : kw;
    const int col = isQ ? (CQ + hq * DH) : (CK + kvh * DH);
    float v = g_pr[(size_t)s * NOUT + col + d];
    float ss = v * v;
#pragma unroll
    for (int o = 16; o; o >>= 1) ss += __shfl_xor_sync(0xffffffffu, ss, o);
    __shared__ float r4[4];
    __shared__ float sh[DH];
    if ((d & 31) == 0) r4[d >> 5] = ss;
    __syncthreads();
    float nv = v * rsqrtf((r4[0]+r4[1]+r4[2]+r4[3]) * (1.f / DH) + 1e-6f) * w[d];
    sh[d] = nv;
    __syncthreads();
    const int dm = d & 63;
    float f = 1.f / powf(10000.f, (float)(2 * dm) * (1.f / DH));
    float cs, sn; sincosf((float)s * f, &sn, &cs);
    float rot = (d < 64) ? -sh[d + 64] : sh[d - 64];
    float rv = nv * cs + rot * sn;

    if (isQ) {
        __half* row = g_qa + ((size_t)hq * SDIM + s) * KQ;
        row[d] = __float2half_rn(rv * 0.08838834764831845f);
        if (d < 32) {
            float bv = 0.f;
            if (hq < NHG) bv = gscale[hq] * (hq < NSYM ? 0.5f : 1.f)
                             * g_pr[(size_t)s * NOUT + CRQ + hq * RDIM + d];
            row[128 + d] = __float2half_rn(bv);
        } else if (d < 64) {
            int r = d - 32;
            float bv = 0.f;
            if (hq < NSYM) bv = gscale[hq] * 0.5f * g_pr[(size_t)s * NOUT + CRK + hq * RDIM + r];
            row[160 + r] = __float2half_rn(bv);
        }
    } else {
        __half kh = __float2half_rn(rv);
#pragma unroll
        for (int e = 0; e < 4; e++) {
            int h = kvh * 4 + e;
            __half* row = g_kb + ((size_t)h * SDIM + s) * KQ;
            row[d] = kh;
            if (d < 32) {
                float bv = (h < NHG) ? g_pr[(size_t)s * NOUT + CRK + h * RDIM + d] : 0.f;
                row[128 + d] = __float2half_rn(bv);
            } else if (d < 64) {
                int r = d - 32;
                float bv = (h < NSYM) ? g_pr[(size_t)s * NOUT + CRQ + h * RDIM + r] : 0.f;
                row[160 + r] = __float2half_rn(bv);
            }
        }
    }
}

// ---------------- Host ----------------
extern "C" void kernel_launch(void* const* d_in, const int* in_sizes, int n_in,
                              void* d_out, int out_size)
{
    const float* x   = (const float*)d_in[0];
    const float* Wq  = (const float*)d_in[1];
    const float* Wk  = (const float*)d_in[2];
    const float* Wv  = (const float*)d_in[3];
    const float* Wo  = (const float*)d_in[4];
    const float* qnw = (const float*)d_in[5];
    const float* knw = (const float*)d_in[6];
    const float* Wrq = (const float*)d_in[7];
    const float* Wrk = (const float*)d_in[8];
    const float* gsc = (const float*)d_in[9];
    float* out = (float*)d_out;

    float* pr;
    __half *xh, *wh, *woh, *aoh;
    cudaGetSymbolAddress((void**)&pr,  g_pr);
    cudaGetSymbolAddress((void**)&xh,  g_xh);
    cudaGetSymbolAddress((void**)&wh,  g_wh);
    cudaGetSymbolAddress((void**)&woh, g_woh);
    cudaGetSymbolAddress((void**)&aoh, g_aoh);

    cudaFuncSetAttribute(gemm1, cudaFuncAttributeMaxDynamicSharedMemorySize, 49152);
    cudaFuncSetAttribute(fattn, cudaFuncAttributeMaxDynamicSharedMemorySize, FSMEM);

    split_all<<<31744, 256>>>(x, Wq, Wk, Wv, Wrq, Wrk, Wo);

    gemm1<<<dim3(NOUT/128, SDIM/64), 256, 49152>>>(xh, wh, pr, NOUT, EDIM);

    normfill2<<<dim3(SDIM, NH + NKV + NKV), 128>>>(qnw, knw, gsc);

    // ncu index 3: fused attention
    fattn<<<dim3(16, NH), 256, FSMEM>>>();

    gemm1<<<dim3(EDIM/128, SDIM/64), 256, 49152>>>(aoh, woh, out, EDIM, EDIM);
}